// round 8
// baseline (speedup 1.0000x reference)
#include <cuda_runtime.h>
#include <cuda_fp16.h>
#include <cstdint>

// Problem constants (CRF_6262062317593): B=512, S=512, T=128
#define CRF_B 512
#define CRF_S 512
#define CRF_T 128
#define SHIFT 5.0f   // ~log(T): per-step normalizer folded into exp(emission)

// Scratch (device globals: allocations are forbidden).
__device__ float g_diff[CRF_B];
__device__ int   g_arrived = 0;   // grid-finish ticket (reset by last CTA)

__device__ __forceinline__ __half2 u32_as_h2(unsigned int u) {
    return *reinterpret_cast<__half2*>(&u);
}

// ---------------------------------------------------------------------------
// Fused kernel: one batch per CTA, 256 threads. Threads j and j+128 split the
// 128-term dot for tag (j&127): each reduces 64 i-terms (32 HFMA2, 32 half2
// E-regs), partials combined through smem. 512 CTAs x 8 warps -> ~28 warps/SM,
// doubling latency hiding vs the 128-thread version.
// ---------------------------------------------------------------------------
__global__ __launch_bounds__(256, 4)
void crf_fused_kernel(const float* __restrict__ em,       // (B,S,T) f32
                      const void*  __restrict__ tags,     // (B,S) i32 or i64
                      const void*  __restrict__ mask,     // (B,S) i32 or u8
                      const float* __restrict__ startT,   // (T)
                      const float* __restrict__ endT,     // (T)
                      const float* __restrict__ trans,    // (T,T)
                      float* __restrict__ out)            // scalar
{
    const int b = blockIdx.x;
    const int j = threadIdx.x;          // 0..255
    const int col = j & 127;            // tag column
    const int half = j >> 7;            // which half of the i-reduction
    const int lane = j & 31;
    const int warp = j >> 5;

    const float* __restrict__ emb = em + (size_t)b * CRF_S * CRF_T;

    __shared__ __align__(16) __half sV[2][CRF_T];
    __shared__ float         sPartial[256];
    __shared__ float         sRed[4];
    __shared__ int           sCnt[256];
    __shared__ unsigned char sMask[CRF_S];
    __shared__ short         sTags[CRF_S];
    __shared__ int           sDet[4];
    __shared__ int           sLast;
    __shared__ float         sFwd;

    // ---- inline dtype detect (validated R2: mask int32 on this harness) ----
    if (j < 64) {
        const unsigned int* tw = (const unsigned int*)tags;
        const unsigned int* mw = (const unsigned int*)mask;
        const int zero = (tw[2 * j + 1] == 0u) ? 1 : 0;
        const int big  = (mw[j] > 1u) ? 1 : 0;
        const unsigned zm = __ballot_sync(0xffffffffu, zero);
        const unsigned bm = __ballot_sync(0xffffffffu, big);
        if (lane == 0) {
            sDet[warp] = __popc(zm);
            sDet[2 + warp] = __popc(bm);
        }
    }
    __syncthreads();
    const int tags_is64 = ((sDet[0] + sDet[1]) >= 48);
    const int mask_is32 = ((sDet[2] + sDet[3]) == 0);

    // ---- stage mask + tags with detected widths ----
    if (mask_is32) {
        const int* m0 = (const int*)mask + (size_t)b * CRF_S;
        for (int s = j; s < CRF_S; s += 256) sMask[s] = (m0[s] != 0);
    } else {
        const unsigned char* m0 = (const unsigned char*)mask + (size_t)b * CRF_S;
        for (int s = j; s < CRF_S; s += 256) sMask[s] = (m0[s] != 0);
    }
    if (tags_is64) {
        const long long* t0 = (const long long*)tags + (size_t)b * CRF_S;
        for (int s = j; s < CRF_S; s += 256) sTags[s] = (short)t0[s];
    } else {
        const int* t0 = (const int*)tags + (size_t)b * CRF_S;
        for (int s = j; s < CRF_S; s += 256) sTags[s] = (short)t0[s];
    }

    // ---- E half-column: Eh[k] = (E[i0+2k][col], E[i0+2k+1][col]), i0=64*half
    __half2 Eh[32];
    {
        const int i0 = 64 * half;
#pragma unroll
        for (int k = 0; k < 32; k++) {
            const float e0 = __expf(trans[(i0 + 2 * k) * CRF_T + col]);
            const float e1 = __expf(trans[(i0 + 2 * k + 1) * CRF_T + col]);
            Eh[k] = __floats2half2_rn(e0, e1);
        }
    }

    // ---- t = 0 init (low half owns state) ----
    const float m00 = startT[0] + emb[0];
    float v = 0.f, w = 0.f, logZ = m00;
    int nstep = 0;
    if (half == 0) {
        v = __expf(startT[col] + emb[col] - m00);
        sV[0][col] = __float2half_rn(v);
        w = __expf(emb[CRF_T + col] - SHIFT);
    }
    __syncthreads();

    for (int s = 1; s < CRF_S; s++) {
        const int p = (s + 1) & 1;
        const int q = s & 1;

        // branchless prefetch of next emissions (low half only)
        float en = 0.f;
        if (half == 0) {
            const int sn = (s + 1 < CRF_S) ? (s + 1) : (CRF_S - 1);
            en = emb[(size_t)sn * CRF_T + col];
        }
        const int mk = sMask[s];

        // 8 LDS.128: 64 halves of v for this half (broadcast, conflict-free)
        const uint4* r = (const uint4*)&sV[p][64 * half];
        __half2 A0 = __half2half2(__ushort_as_half(0));
        __half2 A1 = A0, A2 = A0, A3 = A0;
#pragma unroll
        for (int i = 0; i < 8; i++) {
            const uint4 x = r[i];
            A0 = __hfma2(u32_as_h2(x.x), Eh[4 * i + 0], A0);
            A1 = __hfma2(u32_as_h2(x.y), Eh[4 * i + 1], A1);
            A2 = __hfma2(u32_as_h2(x.z), Eh[4 * i + 2], A2);
            A3 = __hfma2(u32_as_h2(x.w), Eh[4 * i + 3], A3);
        }
        // fp32 combine (fixed order)
        const float2 f0 = __half22float2(A0), f1 = __half22float2(A1);
        const float2 f2 = __half22float2(A2), f3 = __half22float2(A3);
        sPartial[j] = ((f0.x + f0.y) + (f1.x + f1.y))
                    + ((f2.x + f2.y) + (f3.x + f3.y));
        __syncthreads();

        if (half == 0) {
            const float dot = sPartial[col] + sPartial[col + 128];
            float vn = mk ? dot * w : v;
            nstep += mk;
            if ((s & 3) == 0) {        // rescale every 4 steps (fp16 range)
                const float cc = __half2float(sV[p][0]);
                vn *= __fdividef(1.0f, cc);
                logZ += __logf(cc);
            }
            sV[q][col] = __float2half_rn(vn);
            v = vn;
            w = __expf(en - SHIFT);
        }
        __syncthreads();
    }
    logZ += SHIFT * (float)nstep;

    // ---- final: fwd = log(sum_j v_j * exp(end_j)) + logZ (low half) ----
    if (half == 0) {
        const float ej = __expf(endT[col]);
        float t0 = v * ej;
#pragma unroll
        for (int off = 16; off; off >>= 1)
            t0 += __shfl_xor_sync(0xffffffffu, t0, off);
        if (lane == 0) sRed[warp] = t0;
    }
    __syncthreads();
    if (j == 0)
        sFwd = __logf((sRed[0] + sRed[1]) + (sRed[2] + sRed[3])) + logZ;

    // ---- gold score (fp32, fixed-order tree reduce over 256 threads) ----
    {
        float part = 0.f;
        int cnt = 0;
        for (int s = j; s < CRF_S; s += 256) {
            const int mk = sMask[s] ? 1 : 0;
            cnt += mk;
            if (s >= 1 && mk) {
                const int tp = (int)sTags[s - 1];
                const int tc = (int)sTags[s];
                part += trans[tp * CRF_T + tc] + emb[(size_t)s * CRF_T + tc];
            }
        }
        __syncthreads();
        sPartial[j] = part;
        sCnt[j] = cnt;
        __syncthreads();
#pragma unroll
        for (int stride = 128; stride > 0; stride >>= 1) {
            if (j < stride) {
                sPartial[j] += sPartial[j + stride];
                sCnt[j]     += sCnt[j + stride];
            }
            __syncthreads();
        }
        if (j == 0) {
            const int tg0 = (int)sTags[0];
            float gold = sPartial[0] + startT[tg0] + emb[tg0];
            const int seq_end = sCnt[0] - 1;
            gold += endT[(int)sTags[seq_end]];
            g_diff[b] = sFwd - gold;
        }
    }

    // ---- grid-finish: last CTA does the deterministic mean ----
    __syncthreads();
    if (j == 0) {
        __threadfence();
        const int ticket = atomicAdd(&g_arrived, 1);
        sLast = (ticket == CRF_B - 1);
    }
    __syncthreads();
    if (sLast) {
        __threadfence();
        float acc = g_diff[j] + g_diff[j + 256];
        sPartial[j] = acc;
        __syncthreads();
#pragma unroll
        for (int stride = 128; stride > 0; stride >>= 1) {
            if (j < stride) sPartial[j] += sPartial[j + stride];
            __syncthreads();
        }
        if (j == 0) {
            out[0] = sPartial[0] * (1.0f / (float)CRF_B);
            g_arrived = 0;
        }
    }
}

extern "C" void kernel_launch(void* const* d_in, const int* in_sizes, int n_in,
                              void* d_out, int out_size)
{
    const float* emissions = (const float*)d_in[0];
    const void*  tags      = d_in[1];
    const void*  mask      = d_in[2];
    const float* startT    = (const float*)d_in[3];
    const float* endT      = (const float*)d_in[4];
    const float* trans     = (const float*)d_in[5];
    float*       out       = (float*)d_out;

    crf_fused_kernel<<<CRF_B, 256>>>(emissions, tags, mask,
                                     startT, endT, trans, out);
}